// round 13
// baseline (speedup 1.0000x reference)
#include <cuda_runtime.h>
#include <cstdint>

#define BB 1024
#define TT 200
#define EE 128
#define HH 128
#define A1 80
#define A2 40
#define MSTR 132   // padded row stride for M in smem (16B-aligned rows, conflict-free)
#define W2STR 84   // padded col stride for transposed w2 (conflict-free LDS.128)
#define CH 64      // t-chunk per block in k_att
#define TW 8       // timesteps per warp (register-tiled)

typedef unsigned long long ull;

// packed dual-fp32 FMA: acc.{lo,hi} += a.{lo,hi} * b.{lo,hi}
#define FMA2(acc, a, b) asm("fma.rn.f32x2 %0, %1, %2, %0;" : "+l"(acc) : "l"(a), "l"(b))

__device__ __forceinline__ ull pack2(float lo, float hi) {
    ull p; asm("mov.b64 %0, {%1,%2};" : "=l"(p) : "f"(lo), "f"(hi)); return p;
}
__device__ __forceinline__ float unpack_add(ull p) {
    float lo, hi; asm("mov.b64 {%0,%1}, %2;" : "=f"(lo), "=f"(hi) : "l"(p)); return lo + hi;
}

// column remap: storage index j (0..255) -> weight-matrix row.
// Gate col idx and h col idx live in the SAME warp at lanes l and l^16.
__device__ __forceinline__ int rowmap(int j) {
    int l = j & 31, idx = (j >> 5) * 16 + (l & 15);
    return (l & 16) ? (256 + idx) : idx;   // h-gate rows at 256..383, r-gate at 0..127
}

// ---------------- scratch (__device__ globals; no allocation allowed) ----------
__device__ float g_W1q[EE * A1];       // w1[q] + w1[q-k]
__device__ float g_W1k[EE * A1];       // w1[k] - w1[q-k]
__device__ float g_W1p[EE * A1];       // w1[q*k]
__device__ float g_whh_t[EE * 256];    // k-major: [k*256 + j], column j per rowmap(j)
__device__ float g_wih_t[EE * 256];    // e-major, same column mapping
__device__ float g_att[BB * TT];       // attention weights (0 beyond len: never written there)
__device__ float g_gi[(size_t)BB * TT * 256]; // gi preactivations (+bias_ih), rowmap order
__device__ int   g_perm[BB];           // batch rows sorted by length ascending
__device__ int   g_slen[BB];           // sorted (clamped) lengths
__device__ int   g_cut[2];             // prefix counts: len<=82, len<=164
__device__ int   g_goff[4];            // group-id offsets per tier (R=2,4,8)

__device__ __forceinline__ float sigm(float x) {
    return __fdividef(1.f, 1.f + __expf(-x));
}
__device__ __forceinline__ float ftanh(float x) {
    float e = __expf(-2.f * x);
    return __fdividef(1.f - e, 1.f + e);
}

// ---------------- weight prep ----------------
__global__ void k_prep(const float* __restrict__ w1, const float* __restrict__ whh,
                       const float* __restrict__ wih) {
    int i = blockIdx.x * blockDim.x + threadIdx.x;
    if (i < EE * A1) {
        float c = w1[256 * A1 + i];
        g_W1q[i] = w1[i] + c;
        g_W1k[i] = w1[128 * A1 + i] - c;
        g_W1p[i] = w1[384 * A1 + i];
    }
    if (i < EE * 256) {
        int j = i & 255, k = i >> 8;
        int row = rowmap(j);
        g_whh_t[i] = whh[row * EE + k];
        g_wih_t[i] = wih[row * EE + k];
    }
}

// ---------------- single-block counting sort by length (ascending) -------------
__global__ void __launch_bounds__(256) k_sort(const int* __restrict__ len) {
    __shared__ int bins[TT + 1];
    __shared__ int offs[TT + 1];
    int tid = threadIdx.x;
    for (int i = tid; i <= TT; i += 256) bins[i] = 0;
    __syncthreads();
    for (int b = tid; b < BB; b += 256) {
        int l = min(max(len[b], 1), TT);
        atomicAdd(&bins[l], 1);
    }
    __syncthreads();
    if (tid == 0) {
        int run = 0;
        for (int i = 0; i <= TT; i++) {
            offs[i] = run;
            if (i == 83)  g_cut[0] = run;   // #rows len<=82
            if (i == 165) g_cut[1] = run;   // #rows len<=164
            run += bins[i];
        }
    }
    __syncthreads();
    for (int i = tid; i <= TT; i += 256) bins[i] = offs[i];
    __syncthreads();
    for (int b = tid; b < BB; b += 256) {
        int l = min(max(len[b], 1), TT);
        int pos = atomicAdd(&bins[l], 1);
        g_perm[pos] = b;
        g_slen[pos] = l;
    }
}

// ---------------- group-id offsets per tier (R=2 longest, R=4, R=8) ------------
__global__ void k_cuts() {
    if (threadIdx.x == 0 && blockIdx.x == 0) {
        int cA = g_cut[0], cB = g_cut[1];
        g_goff[0] = 0;
        g_goff[1] = (BB - cB + 1) / 2;                 // R=2 groups (len>164)
        g_goff[2] = g_goff[1] + (cB - cA + 3) / 4;     // R=4 groups (83..164)
        g_goff[3] = g_goff[2] + (cA + 7) / 8;          // R=8 groups (<=82)
    }
}

// ---------------- attention MLP + masked softmax (1 block per batch row) -------
__global__ void __launch_bounds__(256, 2) k_att(
    const float* __restrict__ q, const float* __restrict__ keys,
    const int* __restrict__ lens, const float* __restrict__ b1,
    const float* __restrict__ w2, const float* __restrict__ b2,
    const float* __restrict__ wd, const float* __restrict__ bd) {
    extern __shared__ float sm[];
    float* M   = sm;                 // A1 * MSTR = 10560 (j-major, padded)
    float* w2t = M + A1 * MSTR;      // A2 * W2STR = 3360 (transposed, col-major)
    float* qs  = w2t + A2 * W2STR;   // 128
    float* qp  = qs + EE;            // 80
    float* b2s = qp + A1;            // 40
    float* wds = b2s + A2;           // 40
    float* ks  = wds + A2;           // CH*EE = 8192
    float* h1s = ks + CH * EE;       // 8 warps * 4 * 80 = 2560
    float* scs = h1s + 8 * 4 * A1;   // 208
    float* red = scs + 208;          // 256

    int tid = threadIdx.x;
    int b = blockIdx.x;

    if (tid < EE) qs[tid] = q[b * EE + tid];
    for (int i = tid; i < A1 * A2; i += 256) {
        int row = i / A2, c = i % A2;
        w2t[c * W2STR + row] = w2[i];
    }
    if (tid < A2) { b2s[tid] = b2[tid]; wds[tid] = wd[tid]; }
    __syncthreads();

    for (int i = tid; i < EE * A1; i += 256) {
        int j = i % A1, e = i / A1;
        M[j * MSTR + e] = g_W1k[i] + qs[e] * g_W1p[i];
    }
    if (tid < A1) {
        float a = 0.f, bacc = 0.f;
        for (int e = 0; e < EE; e += 2) {
            a    += qs[e]     * g_W1q[e * A1 + tid];
            bacc += qs[e + 1] * g_W1q[(e + 1) * A1 + tid];
        }
        qp[tid] = a + bacc + b1[tid];
    }
    int len = min(max(lens[b], 1), TT);
    __syncthreads();

    float bdv = bd[0];
    int w = tid >> 5, lane = tid & 31;
    const float SCALE = 0.08838834764831845f;  // 1/sqrt(128)

    int j0 = lane, j1 = lane + 32, j2c = (lane < 16) ? (lane + 64) : 64;
    const longlong2* m0p = (const longlong2*)(M + j0 * MSTR);
    const longlong2* m1p = (const longlong2*)(M + j1 * MSTR);
    const longlong2* m2p = (const longlong2*)(M + j2c * MSTR);
    float qp0 = qp[j0], qp1 = qp[j1], qp2 = qp[j2c];
    int jb = lane + 32;
    int jbc = (lane < 8) ? jb : 39;
    float b2v0 = b2s[lane], b2v1 = b2s[jbc];
    float wdv0 = wds[lane], wdv1 = (lane < 8) ? wds[jb] : 0.f;
    const longlong2* w2c0 = (const longlong2*)(w2t + lane * W2STR);
    const longlong2* w2c1 = (const longlong2*)(w2t + jbc * W2STR);
    float* h1w = h1s + w * (4 * A1);
    int base = w * TW;

    for (int t0 = 0; t0 < len; t0 += CH) {
        int nrow = min(CH, len - t0);
        __syncthreads();  // ks reuse guard
        {
            const float4* src = (const float4*)(keys + ((size_t)b * TT + t0) * EE);
            float4* dst = (float4*)ks;
            #pragma unroll
            for (int i = 0; i < CH * (EE / 4) / 256; i++) {
                int v = tid + i * 256;
                int row = v >> 5;
                if (row < nrow) dst[v] = src[v];
            }
        }
        __syncthreads();

        if (base < nrow) {
            // ---- layer 1, packed f32x2, 8 t's register-tiled ----
            ull a0[TW], a1[TW], a2[TW];
            #pragma unroll
            for (int tt = 0; tt < TW; tt++) {
                a0[tt] = pack2(qp0, 0.f); a1[tt] = pack2(qp1, 0.f); a2[tt] = pack2(qp2, 0.f);
            }
            const longlong2* ksw = (const longlong2*)(ks + base * EE);
            #pragma unroll 4
            for (int e4 = 0; e4 < EE / 4; e4++) {
                longlong2 v0 = m0p[e4], v1 = m1p[e4], v2 = m2p[e4];
                #pragma unroll
                for (int tt = 0; tt < TW; tt++) {
                    longlong2 kv = ksw[tt * (EE / 4) + e4];
                    FMA2(a0[tt], (ull)kv.x, (ull)v0.x); FMA2(a0[tt], (ull)kv.y, (ull)v0.y);
                    FMA2(a1[tt], (ull)kv.x, (ull)v1.x); FMA2(a1[tt], (ull)kv.y, (ull)v1.y);
                    FMA2(a2[tt], (ull)kv.x, (ull)v2.x); FMA2(a2[tt], (ull)kv.y, (ull)v2.y);
                }
            }

            // ---- layer 2 + decision, amortized over groups of 4 t's ----
            #pragma unroll
            for (int g = 0; g < 2; g++) {
                if (base + g * 4 >= nrow) break;
                #pragma unroll
                for (int u = 0; u < 4; u++) {
                    int tt = g * 4 + u;
                    h1w[u * A1 + j0] = sigm(unpack_add(a0[tt]));
                    h1w[u * A1 + j1] = sigm(unpack_add(a1[tt]));
                    if (lane < 16) h1w[u * A1 + lane + 64] = sigm(unpack_add(a2[tt]));
                }
                __syncwarp();
                ull p2[4], r2[4];
                #pragma unroll
                for (int u = 0; u < 4; u++) { p2[u] = pack2(b2v0, 0.f); r2[u] = pack2(b2v1, 0.f); }
                #pragma unroll 5
                for (int i4 = 0; i4 < A1 / 4; i4++) {
                    longlong2 w0 = w2c0[i4];
                    longlong2 w1 = w2c1[i4];
                    #pragma unroll
                    for (int u = 0; u < 4; u++) {
                        longlong2 x = *(const longlong2*)&h1w[u * A1 + 4 * i4];
                        FMA2(p2[u], (ull)x.x, (ull)w0.x); FMA2(p2[u], (ull)x.y, (ull)w0.y);
                        FMA2(r2[u], (ull)x.x, (ull)w1.x); FMA2(r2[u], (ull)x.y, (ull)w1.y);
                    }
                }
                #pragma unroll
                for (int u = 0; u < 4; u++) {
                    int tt = g * 4 + u;
                    float h2a = sigm(unpack_add(p2[u]));
                    float h2b = sigm(unpack_add(r2[u]));
                    float c = h2a * wdv0 + h2b * wdv1;
                    #pragma unroll
                    for (int o = 16; o; o >>= 1) c += __shfl_xor_sync(0xffffffffu, c, o);
                    if (lane == 0 && base + tt < nrow) scs[t0 + base + tt] = (c + bdv) * SCALE;
                }
                __syncwarp();
            }
        }
    }
    __syncthreads();

    // masked softmax over t < len
    float m = -1e30f;
    for (int t = tid; t < len; t += 256) m = fmaxf(m, scs[t]);
    red[tid] = m;
    __syncthreads();
    for (int s = 128; s; s >>= 1) { if (tid < s) red[tid] = fmaxf(red[tid], red[tid + s]); __syncthreads(); }
    float mx = red[0];
    __syncthreads();
    float se = 0.f;
    for (int t = tid; t < len; t += 256) { float e = __expf(scs[t] - mx); scs[t] = e; se += e; }
    red[tid] = se;
    __syncthreads();
    for (int s = 128; s; s >>= 1) { if (tid < s) red[tid] += red[tid + s]; __syncthreads(); }
    float inv = __fdividef(1.f, red[0]);
    for (int t = tid; t < len; t += 256) g_att[b * TT + t] = scs[t] * inv;
}

// ---------------- gi precompute: gi[b][t][j] = keys[b][t] . wih_col[j] + bias --
__global__ void __launch_bounds__(256) k_gi(const float* __restrict__ keys,
                                            const int* __restrict__ lens,
                                            const float* __restrict__ bih) {
    __shared__ __align__(16) float ksm[16 * EE];
    int b = blockIdx.x, j = threadIdx.x;
    int len = min(max(lens[b], 1), TT);

    ull wv2[EE / 2];
    #pragma unroll
    for (int k = 0; k < EE / 2; k++)
        wv2[k] = pack2(g_wih_t[(2 * k) * 256 + j], g_wih_t[(2 * k + 1) * 256 + j]);
    float bias = bih[rowmap(j)];

    for (int t0 = 0; t0 < len; t0 += 16) {
        __syncthreads();
        const float4* src = (const float4*)(keys + ((size_t)b * TT + t0) * EE);
        float4* d = (float4*)ksm;
        #pragma unroll
        for (int i = 0; i < 2; i++) {
            int v = j + i * 256;
            int row = v >> 5;
            int t = t0 + row;
            d[v] = (t < TT) ? src[v] : make_float4(0.f, 0.f, 0.f, 0.f);
        }
        __syncthreads();
        #pragma unroll 2
        for (int r = 0; r < 16; r++) {
            int t = t0 + r;
            if (t >= len) break;
            const longlong2* kp = (const longlong2*)(ksm + r * EE);
            ull accA = pack2(bias, 0.f), accB = pack2(0.f, 0.f);
            #pragma unroll
            for (int k4 = 0; k4 < EE / 4; k4++) {
                longlong2 kv = kp[k4];
                FMA2(accA, (ull)kv.x, wv2[2 * k4]);
                FMA2(accB, (ull)kv.y, wv2[2 * k4 + 1]);
            }
            g_gi[((size_t)b * TT + t) * 256 + j] = unpack_add(accA) + unpack_add(accB);
        }
    }
}

// ---------------- AUGRU recurrence body (R rows per block, 1 sync/step) --------
// att is 0 beyond len -> h carries through automatically; no masks needed.
template<int R>
__device__ __forceinline__ void rec_body(
    int start, int cnt, int maxlen, int tid,
    const ull (&wv2)[EE / 2], float bsel,
    float (*hs)[8][EE], float* __restrict__ out) {

    int l = tid & 31;
    bool isH = (l & 16);
    int idx = (tid >> 5) * 16 + (l & 15);   // hidden-unit index this lane owns

    int giOff[R], atOff[R];
    #pragma unroll
    for (int r = 0; r < R; r++) {
        int b = g_perm[start + min(r, cnt - 1)];
        giOff[r] = b * (TT * 256) + tid;
        atOff[r] = b * TT;
    }
    if (tid < 128) {
        #pragma unroll
        for (int r = 0; r < R; r++) hs[0][r][tid] = 0.f;
    }
    __syncthreads();

    // prefetch t=0
    float giv_c[R], av_c[R];
    #pragma unroll
    for (int r = 0; r < R; r++) {
        giv_c[r] = g_gi[giOff[r]];
        av_c[r]  = __ldg(&g_att[atOff[r]]);
    }

    for (int t = 0; t < maxlen; t++) {
        int p = t & 1;
        // prefetch next step (overlaps with this step's compute + sync)
        float giv_n[R], av_n[R];
        #pragma unroll
        for (int r = 0; r < R; r++) { giv_n[r] = 0.f; av_n[r] = 0.f; }
        if (t + 1 < maxlen) {
            #pragma unroll
            for (int r = 0; r < R; r++) {
                giv_n[r] = g_gi[giOff[r] + (t + 1) * 256];
                av_n[r]  = __ldg(&g_att[atOff[r] + t + 1]);
            }
        }

        #pragma unroll
        for (int r = 0; r < R; r++) {
            // dot(h, w_col) with 4 split FMA2 chains
            const longlong2* hp = (const longlong2*)hs[p][r];
            ull aA = pack2(0.f, 0.f), aB = aA, aC = aA, aD = aA;
            #pragma unroll
            for (int k8 = 0; k8 < EE / 8; k8++) {
                longlong2 h0v = hp[2 * k8], h1v = hp[2 * k8 + 1];
                FMA2(aA, (ull)h0v.x, wv2[4 * k8 + 0]);
                FMA2(aB, (ull)h0v.y, wv2[4 * k8 + 1]);
                FMA2(aC, (ull)h1v.x, wv2[4 * k8 + 2]);
                FMA2(aD, (ull)h1v.y, wv2[4 * k8 + 3]);
            }
            float acc = (unpack_add(aA) + unpack_add(aB)) + (unpack_add(aC) + unpack_add(aD));

            // r-lanes compute rv; h-lanes get partner's rv via shfl
            float rv = sigm(giv_c[r] + bsel + acc);
            float rp = __shfl_xor_sync(0xffffffffu, rv, 16);
            if (isH) {
                float nw = ftanh(giv_c[r] + rp * (acc + bsel));   // bsel = b_hh_h here
                float h0 = hs[p][r][idx];
                hs[1 - p][r][idx] = fmaf(av_c[r], nw - h0, h0);   // av=0 past len => carry
            }
        }
        #pragma unroll
        for (int r = 0; r < R; r++) { giv_c[r] = giv_n[r]; av_c[r] = av_n[r]; }
        __syncthreads();
    }

    int f = maxlen & 1;
    if (tid < 128) {
        #pragma unroll
        for (int r = 0; r < R; r++) {
            int b = g_perm[start + min(r, cnt - 1)];
            out[b * HH + tid] = hs[f][r][tid];
        }
    }
}

__global__ void __launch_bounds__(256, 1) k_rec(const float* __restrict__ bhh,
                                                float* __restrict__ out) {
    __shared__ __align__(16) float hs[2][8][EE];

    int bid = blockIdx.x;
    if (bid >= g_goff[3]) return;

    int tid = threadIdx.x;
    float bsel = bhh[rowmap(tid)];   // r-lane: b_hh_r[idx]; h-lane: b_hh_h[idx]

    ull wv2[EE / 2];  // this thread's w_hh column, packed register-resident
    #pragma unroll
    for (int k = 0; k < EE / 2; k++)
        wv2[k] = pack2(g_whh_t[(2 * k) * 256 + tid], g_whh_t[(2 * k + 1) * 256 + tid]);

    int cA = g_cut[0], cB = g_cut[1];
    int R, end, lo;
    if (bid < g_goff[1])      { R = 2; int g = bid;              end = BB - 1 - 2 * g; lo = cB; }
    else if (bid < g_goff[2]) { R = 4; int g = bid - g_goff[1];  end = cB - 1 - 4 * g; lo = cA; }
    else                      { R = 8; int g = bid - g_goff[2];  end = cA - 1 - 8 * g; lo = 0;  }
    int start = max(end - R + 1, lo);
    int cnt = end - start + 1;
    int maxlen = g_slen[end];

    switch (R) {
        case 2:  rec_body<2>(start, cnt, maxlen, tid, wv2, bsel, hs, out); break;
        case 4:  rec_body<4>(start, cnt, maxlen, tid, wv2, bsel, hs, out); break;
        default: rec_body<8>(start, cnt, maxlen, tid, wv2, bsel, hs, out); break;
    }
}

// ---------------- launch (exactly 6 kernels) ----------------
extern "C" void kernel_launch(void* const* d_in, const int* in_sizes, int n_in,
                              void* d_out, int out_size) {
    const float* q    = (const float*)d_in[0];
    const float* keys = (const float*)d_in[1];
    const int*   klen = (const int*)d_in[2];
    const float* w1   = (const float*)d_in[3];
    const float* b1   = (const float*)d_in[4];
    const float* w2   = (const float*)d_in[5];
    const float* b2   = (const float*)d_in[6];
    const float* wd   = (const float*)d_in[7];
    const float* bd   = (const float*)d_in[8];
    const float* wih  = (const float*)d_in[9];
    const float* whh  = (const float*)d_in[10];
    const float* bih  = (const float*)d_in[11];
    const float* bhh  = (const float*)d_in[12];
    float* out = (float*)d_out;

    k_prep<<<128, 256>>>(w1, whh, wih);
    k_sort<<<1, 256>>>(klen);
    k_cuts<<<1, 32>>>();

    const int ATT_SMEM = 25424 * 4;  // 101,696 B dynamic -> 2 blocks/SM
    cudaFuncSetAttribute(k_att, cudaFuncAttributeMaxDynamicSharedMemorySize, ATT_SMEM);
    k_att<<<BB, 256, ATT_SMEM>>>(q, keys, klen, b1, w2, b2, wd, bd);
    k_gi<<<BB, 256>>>(keys, klen, bih);
    k_rec<<<640, 256>>>(bhh, out);
}

// round 14
// speedup vs baseline: 1.1067x; 1.1067x over previous
#include <cuda_runtime.h>
#include <cstdint>

#define BB 1024
#define TT 200
#define EE 128
#define HH 128
#define A1 80
#define A2 40
#define MSTR 132   // padded row stride for M in smem (16B-aligned rows)
#define W2STR 84   // padded col stride for transposed w2 (conflict-free LDS.128)
#define CH 64      // t-chunk per block in k_att
#define TW 8       // timesteps per warp (register-tiled)

typedef unsigned long long ull;

// packed dual-fp32 FMA: acc.{lo,hi} += a.{lo,hi} * b.{lo,hi}
#define FMA2(acc, a, b) asm("fma.rn.f32x2 %0, %1, %2, %0;" : "+l"(acc) : "l"(a), "l"(b))

__device__ __forceinline__ ull pack2(float lo, float hi) {
    ull p; asm("mov.b64 %0, {%1,%2};" : "=l"(p) : "f"(lo), "f"(hi)); return p;
}
__device__ __forceinline__ float unpack_add(ull p) {
    float lo, hi; asm("mov.b64 {%0,%1}, %2;" : "=f"(lo), "=f"(hi) : "l"(p)); return lo + hi;
}

// column remap: storage index j (0..255) -> weight-matrix row.
// Gate col idx and h col idx live in the SAME warp at lanes l and l^16.
__device__ __forceinline__ int rowmap(int j) {
    int l = j & 31, idx = (j >> 5) * 16 + (l & 15);
    return (l & 16) ? (256 + idx) : idx;   // h-gate rows at 256..383, r-gate at 0..127
}

// ---------------- scratch (__device__ globals; no allocation allowed) ----------
__device__ float g_W1q[EE * A1];       // w1[q] + w1[q-k]
__device__ float g_W1k[EE * A1];       // w1[k] - w1[q-k]
__device__ float g_W1p[EE * A1];       // w1[q*k]
__device__ float g_whh_t[EE * 256];    // k-major: [k*256 + j], column j per rowmap(j)
__device__ float g_wih_t[EE * 256];    // e-major, same column mapping
__device__ float g_att[BB * TT];       // attention weights (0 beyond len: never written there)
__device__ float g_gi[(size_t)BB * TT * 256]; // gi preactivations (+bias_ih), rowmap order
__device__ int   g_perm[BB];           // batch rows sorted by length ascending
__device__ int   g_slen[BB];           // sorted (clamped) lengths
__device__ int   g_cut[2];             // prefix counts: len<=82, len<=164
__device__ int   g_goff[4];            // group-id offsets per tier (R=2,4,4)

__device__ __forceinline__ float sigm(float x) {
    return __fdividef(1.f, 1.f + __expf(-x));
}
__device__ __forceinline__ float ftanh(float x) {
    float e = __expf(-2.f * x);
    return __fdividef(1.f - e, 1.f + e);
}

// ---------------- weight prep + counting sort + tier offsets (one kernel) ------
__global__ void __launch_bounds__(256) k_prepsort(
    const float* __restrict__ w1, const float* __restrict__ whh,
    const float* __restrict__ wih, const int* __restrict__ len) {
    int tid = threadIdx.x;
    int i = blockIdx.x * blockDim.x + tid;

    // weight transforms (covers 128*256 = 32768 = EE*256 exactly)
    if (i < EE * A1) {
        float c = w1[256 * A1 + i];
        g_W1q[i] = w1[i] + c;
        g_W1k[i] = w1[128 * A1 + i] - c;
        g_W1p[i] = w1[384 * A1 + i];
    }
    if (i < EE * 256) {
        int j = i & 255, k = i >> 8;
        int row = rowmap(j);
        g_whh_t[i] = whh[row * EE + k];
        g_wih_t[i] = wih[row * EE + k];
    }

    // block 0: counting sort by length (ascending) + tier group offsets
    if (blockIdx.x == 0) {
        __shared__ int bins[TT + 1];
        __shared__ int offs[TT + 1];
        for (int v = tid; v <= TT; v += 256) bins[v] = 0;
        __syncthreads();
        for (int b = tid; b < BB; b += 256) {
            int l = min(max(len[b], 1), TT);
            atomicAdd(&bins[l], 1);
        }
        __syncthreads();
        if (tid == 0) {
            int run = 0, cA = 0, cB = 0;
            for (int v = 0; v <= TT; v++) {
                offs[v] = run;
                if (v == 83)  cA = run;   // #rows len<=82
                if (v == 165) cB = run;   // #rows len<=164
                run += bins[v];
            }
            g_cut[0] = cA;
            g_cut[1] = cB;
            g_goff[0] = 0;
            g_goff[1] = (BB - cB + 1) / 2;                 // R=2 groups (len>164)
            g_goff[2] = g_goff[1] + (cB - cA + 3) / 4;     // R=4 groups (83..164)
            g_goff[3] = g_goff[2] + (cA + 3) / 4;          // R=4 groups (<=82)
        }
        __syncthreads();
        for (int v = tid; v <= TT; v += 256) bins[v] = offs[v];
        __syncthreads();
        for (int b = tid; b < BB; b += 256) {
            int l = min(max(len[b], 1), TT);
            int pos = atomicAdd(&bins[l], 1);
            g_perm[pos] = b;
            g_slen[pos] = l;
        }
    }
}

// ---------------- attention MLP + masked softmax (1 block per batch row) -------
__global__ void __launch_bounds__(256, 2) k_att(
    const float* __restrict__ q, const float* __restrict__ keys,
    const int* __restrict__ lens, const float* __restrict__ b1,
    const float* __restrict__ w2, const float* __restrict__ b2,
    const float* __restrict__ wd, const float* __restrict__ bd) {
    extern __shared__ float sm[];
    float* M   = sm;                 // A1 * MSTR = 10560 (j-major, padded)
    float* w2t = M + A1 * MSTR;      // A2 * W2STR = 3360 (transposed, col-major)
    float* qs  = w2t + A2 * W2STR;   // 128
    float* qp  = qs + EE;            // 80
    float* b2s = qp + A1;            // 40
    float* wds = b2s + A2;           // 40
    float* ks  = wds + A2;           // CH*EE = 8192
    float* h1s = ks + CH * EE;       // 8 warps * 4 * 80 = 2560
    float* scs = h1s + 8 * 4 * A1;   // 208
    float* red = scs + 208;          // 256

    int tid = threadIdx.x;
    int b = blockIdx.x;

    if (tid < EE) qs[tid] = q[b * EE + tid];
    for (int i = tid; i < A1 * A2; i += 256) {
        int row = i / A2, c = i % A2;
        w2t[c * W2STR + row] = w2[i];
    }
    if (tid < A2) { b2s[tid] = b2[tid]; wds[tid] = wd[tid]; }
    __syncthreads();

    for (int i = tid; i < EE * A1; i += 256) {
        int j = i % A1, e = i / A1;
        M[j * MSTR + e] = g_W1k[i] + qs[e] * g_W1p[i];
    }
    if (tid < A1) {
        float a = 0.f, bacc = 0.f;
        for (int e = 0; e < EE; e += 2) {
            a    += qs[e]     * g_W1q[e * A1 + tid];
            bacc += qs[e + 1] * g_W1q[(e + 1) * A1 + tid];
        }
        qp[tid] = a + bacc + b1[tid];
    }
    int len = min(max(lens[b], 1), TT);
    __syncthreads();

    float bdv = bd[0];
    int w = tid >> 5, lane = tid & 31;
    const float SCALE = 0.08838834764831845f;  // 1/sqrt(128)

    int j0 = lane, j1 = lane + 32, j2c = (lane < 16) ? (lane + 64) : 64;
    const longlong2* m0p = (const longlong2*)(M + j0 * MSTR);
    const longlong2* m1p = (const longlong2*)(M + j1 * MSTR);
    const longlong2* m2p = (const longlong2*)(M + j2c * MSTR);
    float qp0 = qp[j0], qp1 = qp[j1], qp2 = qp[j2c];
    int jb = lane + 32;
    int jbc = (lane < 8) ? jb : 39;
    float b2v0 = b2s[lane], b2v1 = b2s[jbc];
    float wdv0 = wds[lane], wdv1 = (lane < 8) ? wds[jb] : 0.f;
    const longlong2* w2c0 = (const longlong2*)(w2t + lane * W2STR);
    const longlong2* w2c1 = (const longlong2*)(w2t + jbc * W2STR);
    float* h1w = h1s + w * (4 * A1);
    int base = w * TW;

    for (int t0 = 0; t0 < len; t0 += CH) {
        int nrow = min(CH, len - t0);
        __syncthreads();  // ks reuse guard
        {
            const float4* src = (const float4*)(keys + ((size_t)b * TT + t0) * EE);
            float4* dst = (float4*)ks;
            #pragma unroll
            for (int i = 0; i < CH * (EE / 4) / 256; i++) {
                int v = tid + i * 256;
                int row = v >> 5;
                if (row < nrow) dst[v] = src[v];
            }
        }
        __syncthreads();

        if (base < nrow) {
            // ---- layer 1, packed f32x2, 8 t's register-tiled ----
            ull a0[TW], a1[TW], a2[TW];
            #pragma unroll
            for (int tt = 0; tt < TW; tt++) {
                a0[tt] = pack2(qp0, 0.f); a1[tt] = pack2(qp1, 0.f); a2[tt] = pack2(qp2, 0.f);
            }
            const longlong2* ksw = (const longlong2*)(ks + base * EE);
            #pragma unroll 4
            for (int e4 = 0; e4 < EE / 4; e4++) {
                longlong2 v0 = m0p[e4], v1 = m1p[e4], v2 = m2p[e4];
                #pragma unroll
                for (int tt = 0; tt < TW; tt++) {
                    longlong2 kv = ksw[tt * (EE / 4) + e4];
                    FMA2(a0[tt], (ull)kv.x, (ull)v0.x); FMA2(a0[tt], (ull)kv.y, (ull)v0.y);
                    FMA2(a1[tt], (ull)kv.x, (ull)v1.x); FMA2(a1[tt], (ull)kv.y, (ull)v1.y);
                    FMA2(a2[tt], (ull)kv.x, (ull)v2.x); FMA2(a2[tt], (ull)kv.y, (ull)v2.y);
                }
            }

            // ---- layer 2 + decision, amortized over groups of 4 t's ----
            #pragma unroll
            for (int g = 0; g < 2; g++) {
                if (base + g * 4 >= nrow) break;
                #pragma unroll
                for (int u = 0; u < 4; u++) {
                    int tt = g * 4 + u;
                    h1w[u * A1 + j0] = sigm(unpack_add(a0[tt]));
                    h1w[u * A1 + j1] = sigm(unpack_add(a1[tt]));
                    if (lane < 16) h1w[u * A1 + lane + 64] = sigm(unpack_add(a2[tt]));
                }
                __syncwarp();
                ull p2[4], r2[4];
                #pragma unroll
                for (int u = 0; u < 4; u++) { p2[u] = pack2(b2v0, 0.f); r2[u] = pack2(b2v1, 0.f); }
                #pragma unroll 5
                for (int i4 = 0; i4 < A1 / 4; i4++) {
                    longlong2 w0 = w2c0[i4];
                    longlong2 w1 = w2c1[i4];
                    #pragma unroll
                    for (int u = 0; u < 4; u++) {
                        longlong2 x = *(const longlong2*)&h1w[u * A1 + 4 * i4];
                        FMA2(p2[u], (ull)x.x, (ull)w0.x); FMA2(p2[u], (ull)x.y, (ull)w0.y);
                        FMA2(r2[u], (ull)x.x, (ull)w1.x); FMA2(r2[u], (ull)x.y, (ull)w1.y);
                    }
                }
                #pragma unroll
                for (int u = 0; u < 4; u++) {
                    int tt = g * 4 + u;
                    float h2a = sigm(unpack_add(p2[u]));
                    float h2b = sigm(unpack_add(r2[u]));
                    float c = h2a * wdv0 + h2b * wdv1;
                    #pragma unroll
                    for (int o = 16; o; o >>= 1) c += __shfl_xor_sync(0xffffffffu, c, o);
                    if (lane == 0 && base + tt < nrow) scs[t0 + base + tt] = (c + bdv) * SCALE;
                }
                __syncwarp();
            }
        }
    }
    __syncthreads();

    // masked softmax over t < len
    float m = -1e30f;
    for (int t = tid; t < len; t += 256) m = fmaxf(m, scs[t]);
    red[tid] = m;
    __syncthreads();
    for (int s = 128; s; s >>= 1) { if (tid < s) red[tid] = fmaxf(red[tid], red[tid + s]); __syncthreads(); }
    float mx = red[0];
    __syncthreads();
    float se = 0.f;
    for (int t = tid; t < len; t += 256) { float e = __expf(scs[t] - mx); scs[t] = e; se += e; }
    red[tid] = se;
    __syncthreads();
    for (int s = 128; s; s >>= 1) { if (tid < s) red[tid] += red[tid + s]; __syncthreads(); }
    float inv = __fdividef(1.f, red[0]);
    for (int t = tid; t < len; t += 256) g_att[b * TT + t] = scs[t] * inv;
}

// ---------------- gi precompute: gi[b][t][j] = keys[b][t] . wih_col[j] + bias --
__global__ void __launch_bounds__(256) k_gi(const float* __restrict__ keys,
                                            const int* __restrict__ lens,
                                            const float* __restrict__ bih) {
    __shared__ __align__(16) float ksm[16 * EE];
    int b = blockIdx.x, j = threadIdx.x;
    int len = min(max(lens[b], 1), TT);

    ull wv2[EE / 2];
    #pragma unroll
    for (int k = 0; k < EE / 2; k++)
        wv2[k] = pack2(g_wih_t[(2 * k) * 256 + j], g_wih_t[(2 * k + 1) * 256 + j]);
    float bias = bih[rowmap(j)];

    for (int t0 = 0; t0 < len; t0 += 16) {
        __syncthreads();
        const float4* src = (const float4*)(keys + ((size_t)b * TT + t0) * EE);
        float4* d = (float4*)ksm;
        #pragma unroll
        for (int i = 0; i < 2; i++) {
            int v = j + i * 256;
            int row = v >> 5;
            int t = t0 + row;
            d[v] = (t < TT) ? src[v] : make_float4(0.f, 0.f, 0.f, 0.f);
        }
        __syncthreads();
        #pragma unroll 2
        for (int r = 0; r < 16; r++) {
            int t = t0 + r;
            if (t >= len) break;
            const longlong2* kp = (const longlong2*)(ksm + r * EE);
            ull accA = pack2(bias, 0.f), accB = pack2(0.f, 0.f);
            #pragma unroll
            for (int k4 = 0; k4 < EE / 4; k4++) {
                longlong2 kv = kp[k4];
                FMA2(accA, (ull)kv.x, wv2[2 * k4]);
                FMA2(accB, (ull)kv.y, wv2[2 * k4 + 1]);
            }
            g_gi[((size_t)b * TT + t) * 256 + j] = unpack_add(accA) + unpack_add(accB);
        }
    }
}

// ---------------- AUGRU recurrence body (R<=4 rows per block, 1 sync/step) -----
// att is 0 beyond len -> h carries through automatically; no masks needed.
template<int R>
__device__ __forceinline__ void rec_body(
    int start, int cnt, int maxlen, int tid,
    const ull (&wv2)[EE / 2], float bsel,
    float (*hs)[4][EE], float* __restrict__ out) {

    int l = tid & 31;
    bool isH = (l & 16);
    int idx = (tid >> 5) * 16 + (l & 15);   // hidden-unit index this lane owns

    int giOff[R], atOff[R];
    #pragma unroll
    for (int r = 0; r < R; r++) {
        int b = g_perm[start + min(r, cnt - 1)];
        giOff[r] = b * (TT * 256) + tid;
        atOff[r] = b * TT;
    }
    if (tid < 128) {
        #pragma unroll
        for (int r = 0; r < R; r++) hs[0][r][tid] = 0.f;
    }
    __syncthreads();

    // prefetch t=0
    float giv_c[R], av_c[R];
    #pragma unroll
    for (int r = 0; r < R; r++) {
        giv_c[r] = g_gi[giOff[r]];
        av_c[r]  = __ldg(&g_att[atOff[r]]);
    }

    for (int t = 0; t < maxlen; t++) {
        int p = t & 1;
        // prefetch next step (overlaps with this step's compute + sync)
        float giv_n[R], av_n[R];
        #pragma unroll
        for (int r = 0; r < R; r++) { giv_n[r] = 0.f; av_n[r] = 0.f; }
        if (t + 1 < maxlen) {
            #pragma unroll
            for (int r = 0; r < R; r++) {
                giv_n[r] = g_gi[giOff[r] + (t + 1) * 256];
                av_n[r]  = __ldg(&g_att[atOff[r] + t + 1]);
            }
        }

        #pragma unroll
        for (int r = 0; r < R; r++) {
            // dot(h, w_col) with 4 split FMA2 chains
            const longlong2* hp = (const longlong2*)hs[p][r];
            ull aA = pack2(0.f, 0.f), aB = aA, aC = aA, aD = aA;
            #pragma unroll
            for (int k8 = 0; k8 < EE / 8; k8++) {
                longlong2 h0v = hp[2 * k8], h1v = hp[2 * k8 + 1];
                FMA2(aA, (ull)h0v.x, wv2[4 * k8 + 0]);
                FMA2(aB, (ull)h0v.y, wv2[4 * k8 + 1]);
                FMA2(aC, (ull)h1v.x, wv2[4 * k8 + 2]);
                FMA2(aD, (ull)h1v.y, wv2[4 * k8 + 3]);
            }
            float acc = (unpack_add(aA) + unpack_add(aB)) + (unpack_add(aC) + unpack_add(aD));

            // r-lanes compute rv; h-lanes get partner's rv via shfl
            float rv = sigm(giv_c[r] + bsel + acc);
            float rp = __shfl_xor_sync(0xffffffffu, rv, 16);
            if (isH) {
                float nw = ftanh(giv_c[r] + rp * (acc + bsel));   // bsel = b_hh_h here
                float h0 = hs[p][r][idx];
                hs[1 - p][r][idx] = fmaf(av_c[r], nw - h0, h0);   // av=0 past len => carry
            }
        }
        #pragma unroll
        for (int r = 0; r < R; r++) { giv_c[r] = giv_n[r]; av_c[r] = av_n[r]; }
        __syncthreads();
    }

    int f = maxlen & 1;
    if (tid < 128) {
        #pragma unroll
        for (int r = 0; r < R; r++) {
            int b = g_perm[start + min(r, cnt - 1)];
            out[b * HH + tid] = hs[f][r][tid];
        }
    }
}

__global__ void __launch_bounds__(256, 1) k_rec(const float* __restrict__ bhh,
                                                float* __restrict__ out) {
    __shared__ __align__(16) float hs[2][4][EE];

    int bid = blockIdx.x;
    if (bid >= g_goff[3]) return;

    int tid = threadIdx.x;
    float bsel = bhh[rowmap(tid)];   // r-lane: b_hh_r[idx]; h-lane: b_hh_h[idx]

    ull wv2[EE / 2];  // this thread's w_hh column, packed register-resident
    #pragma unroll
    for (int k = 0; k < EE / 2; k++)
        wv2[k] = pack2(g_whh_t[(2 * k) * 256 + tid], g_whh_t[(2 * k + 1) * 256 + tid]);

    int cA = g_cut[0], cB = g_cut[1];
    int R, end, lo;
    if (bid < g_goff[1])      { R = 2; int g = bid;              end = BB - 1 - 2 * g; lo = cB; }
    else if (bid < g_goff[2]) { R = 4; int g = bid - g_goff[1];  end = cB - 1 - 4 * g; lo = cA; }
    else                      { R = 4; int g = bid - g_goff[2];  end = cA - 1 - 4 * g; lo = 0;  }
    int start = max(end - R + 1, lo);
    int cnt = end - start + 1;
    int maxlen = g_slen[end];

    if (R == 2) rec_body<2>(start, cnt, maxlen, tid, wv2, bsel, hs, out);
    else        rec_body<4>(start, cnt, maxlen, tid, wv2, bsel, hs, out);
}

// ---------------- launch (exactly 4 kernels) ----------------
extern "C" void kernel_launch(void* const* d_in, const int* in_sizes, int n_in,
                              void* d_out, int out_size) {
    const float* q    = (const float*)d_in[0];
    const float* keys = (const float*)d_in[1];
    const int*   klen = (const int*)d_in[2];
    const float* w1   = (const float*)d_in[3];
    const float* b1   = (const float*)d_in[4];
    const float* w2   = (const float*)d_in[5];
    const float* b2   = (const float*)d_in[6];
    const float* wd   = (const float*)d_in[7];
    const float* bd   = (const float*)d_in[8];
    const float* wih  = (const float*)d_in[9];
    const float* whh  = (const float*)d_in[10];
    const float* bih  = (const float*)d_in[11];
    const float* bhh  = (const float*)d_in[12];
    float* out = (float*)d_out;

    k_prepsort<<<128, 256>>>(w1, whh, wih, klen);

    const int ATT_SMEM = 25424 * 4;  // 101,696 B dynamic -> 2 blocks/SM
    cudaFuncSetAttribute(k_att, cudaFuncAttributeMaxDynamicSharedMemorySize, ATT_SMEM);
    k_att<<<BB, 256, ATT_SMEM>>>(q, keys, klen, b1, w2, b2, wd, bd);
    k_gi<<<BB, 256>>>(keys, klen, bih);
    k_rec<<<640, 256>>>(bhh, out);
}